// round 11
// baseline (speedup 1.0000x reference)
#include <cuda_runtime.h>

// ---------------- problem constants ----------------
#define BB    4
#define NANCH 211200
#define CC    256
#define HH    200
#define WW    176
#define KK    4096

#define NBOX      (BB * NANCH)          // 844,800
#define BOX_ELEMS (NBOX * 7)            // 5,913,600

#define THREADS   512
#define KPT       (KK / THREADS)        // 8 points per thread

#define GATHER_BLOCKS (BB * CC)                 // 1024, one CTA per plane
#define DECODE_BLOCKS (NBOX / THREADS)          // 1650 (exact)
#define TOTAL_BLOCKS  (GATHER_BLOCKS + DECODE_BLOCKS)  // 2674

#define PLANE_FLOATS  (HH * WW)         // 35,200
#define HALF_SPLIT    (100 * WW)        // 17,600 : first offset of rows>=100
#define HALF_A_FLOATS (101 * WW)        // 17,776 (rows 0..100, incl boundary)
#define HALF_B_FLOATS (100 * WW)        // 17,600 (rows 100..199)
#define SMEM_BYTES    (HALF_A_FLOATS * 4)       // 71,104 -> 3 CTAs/SM

// Precomputed per-(b,k): 4 clamped corner offsets + 4 validity-folded weights.
__device__ ushort4 g_off[BB * KK];
__device__ float4  g_wgt[BB * KK];

// ---------------- kernel 1: per-keypoint precompute ----------------
__global__ void precompute_kernel(const float* __restrict__ kp)
{
    int i = blockIdx.x * blockDim.x + threadIdx.x;
    if (i >= BB * KK) return;

    float x = kp[i * 3 + 0];
    float y = kp[i * 3 + 1];

    // --- coord transform (matches reference exactly) ---
    const float px = 0.05f * 8.0f;              // base_pixel_size * STRIDE
    float idx_x = x / px;
    float idx_y = (y + 40.0f) / px;
    idx_x = fminf(fmaxf(idx_x, 0.0f), (float)(WW - 1));
    idx_y = fminf(fmaxf(idx_y, 0.0f), (float)(HH - 1));
    float nx = 2.0f * (idx_x / (float)(WW - 2)) - 1.0f;
    float ny = 2.0f * (idx_y / (float)(HH - 2)) - 1.0f;
    // grid = flip(indices): width driven by ny, height by nx
    float ix = (ny + 1.0f) * 0.5f * (float)(WW - 1);
    float iy = (nx + 1.0f) * 0.5f * (float)(HH - 1);

    float x0f = floorf(ix);
    float y0f = floorf(iy);
    float wx = ix - x0f;
    float wy = iy - y0f;
    int x0 = (int)x0f, y0 = (int)y0f;
    int x1 = x0 + 1,   y1 = y0 + 1;

    float vx0 = (x0 >= 0 && x0 <= WW - 1) ? 1.0f : 0.0f;
    float vx1 = (x1 >= 0 && x1 <= WW - 1) ? 1.0f : 0.0f;
    float vy0 = (y0 >= 0 && y0 <= HH - 1) ? 1.0f : 0.0f;
    float vy1 = (y1 >= 0 && y1 <= HH - 1) ? 1.0f : 0.0f;

    int x0c = min(max(x0, 0), WW - 1);
    int x1c = min(max(x1, 0), WW - 1);
    int y0c = min(max(y0, 0), HH - 1);
    int y1c = min(max(y1, 0), HH - 1);

    g_off[i] = make_ushort4((unsigned short)(y0c * WW + x0c),
                            (unsigned short)(y0c * WW + x1c),
                            (unsigned short)(y1c * WW + x0c),
                            (unsigned short)(y1c * WW + x1c));
    g_wgt[i] = make_float4((1.0f - wx) * (1.0f - wy) * (vx0 * vy0),
                           wx          * (1.0f - wy) * (vx1 * vy0),
                           (1.0f - wx) * wy          * (vx0 * vy1),
                           wx          * wy          * (vx1 * vy1));
}

// ---------------- decode for one box ----------------
__device__ __forceinline__ void decode_one(const float* __restrict__ deltas,
                                           const float* __restrict__ anchors,
                                           float* __restrict__ out, int box)
{
    size_t base = (size_t)box * 7;
    float d0 = deltas[base + 0], d1 = deltas[base + 1], d2 = deltas[base + 2];
    float d3 = deltas[base + 3], d4 = deltas[base + 4], d5 = deltas[base + 5];
    float d6 = deltas[base + 6];
    float a0 = anchors[base + 0], a1 = anchors[base + 1], a2 = anchors[base + 2];
    float a3 = anchors[base + 3], a4 = anchors[base + 4], a5 = anchors[base + 5];
    float a6 = anchors[base + 6];

    float dnorm = sqrtf(a3 * a3 + a4 * a4);

    out[base + 0] = d0 * dnorm + a0;
    out[base + 1] = d1 * dnorm + a1;
    out[base + 2] = d2 * a5 + a2;
    out[base + 3] = expf(d3) * a3;
    out[base + 4] = expf(d4) * a4;
    out[base + 5] = expf(d5) * a5;
    out[base + 6] = d6 + a6;
}

// ---------------- staging helper ----------------
__device__ __forceinline__ void stage(const float* __restrict__ src,
                                      float* __restrict__ smem, int nfloats)
{
    const float4* __restrict__ s4 = (const float4*)src;
    float4* __restrict__ d4 = (float4*)smem;
    const int N4 = nfloats / 4;                 // 4444 or 4400
    int i = threadIdx.x;
    #pragma unroll 8
    for (int t = 0; t < 8; t++, i += THREADS)   // 8*512 = 4096
        d4[i] = s4[i];
    for (; i < N4; i += THREADS)
        d4[i] = s4[i];
}

// ---------------- gather: one (b,c) plane, two staged halves ----------------
__device__ __forceinline__ void gather_plane(int pl,
                                             const float* __restrict__ fm,
                                             float* __restrict__ bev,
                                             float* __restrict__ smem)
{
    const int b = pl >> 8;                      // pl / CC
    const float* __restrict__ pf = fm + (size_t)pl * PLANE_FLOATS;
    const int base = b * KK + threadIdx.x;

    float r[KPT];

    // ---- half A: rows [0, 101) ----
    stage(pf, smem, HALF_A_FLOATS);
    __syncthreads();
    #pragma unroll
    for (int t = 0; t < KPT; t++) {
        int idx = base + t * THREADS;
        ushort4 o = __ldg(&g_off[idx]);
        if (o.x < HALF_SPLIT) {
            float4 w = __ldg(&g_wgt[idx]);
            r[t] = smem[o.x] * w.x + smem[o.y] * w.y
                 + smem[o.z] * w.z + smem[o.w] * w.w;
        }
    }
    __syncthreads();

    // ---- half B: rows [100, 200), rebased by HALF_SPLIT ----
    stage(pf + HALF_SPLIT, smem, HALF_B_FLOATS);
    __syncthreads();
    const float* __restrict__ pb = smem - HALF_SPLIT;
    #pragma unroll
    for (int t = 0; t < KPT; t++) {
        int idx = base + t * THREADS;
        ushort4 o = __ldg(&g_off[idx]);
        if (o.x >= HALF_SPLIT) {
            float4 w = __ldg(&g_wgt[idx]);
            r[t] = pb[o.x] * w.x + pb[o.y] * w.y
                 + pb[o.z] * w.z + pb[o.w] * w.w;
        }
    }

    // ---- dense coalesced write, each output written exactly once ----
    float* __restrict__ orow = bev + (size_t)pl * KK;
    #pragma unroll
    for (int t = 0; t < KPT; t++)
        orow[t * THREADS + threadIdx.x] = r[t];
}

// ---------------- fused kernel ----------------
// Interleave gather / decode so each scheduling wave mixes streaming decode
// with smem gather work.
__global__ void __launch_bounds__(THREADS, 3)
fused_kernel(const float* __restrict__ deltas,
             const float* __restrict__ anchors,
             const float* __restrict__ fm,
             float* __restrict__ boxes,
             float* __restrict__ bev)
{
    extern __shared__ float smem[];
    const int blk = blockIdx.x;

    int gather_idx = -1, decode_idx = -1;
    if (blk < 2 * GATHER_BLOCKS) {              // first 2048 blocks alternate
        if (blk & 1) decode_idx = blk >> 1;
        else         gather_idx = blk >> 1;
    } else {
        decode_idx = blk - GATHER_BLOCKS;       // 1024 .. 1649
    }

    if (gather_idx >= 0) {
        gather_plane(gather_idx, fm, bev, smem);
    } else {
        int box = decode_idx * THREADS + threadIdx.x;
        decode_one(deltas, anchors, boxes, box);
    }
}

// ---------------- launch ----------------
extern "C" void kernel_launch(void* const* d_in, const int* in_sizes, int n_in,
                              void* d_out, int out_size)
{
    const float* deltas  = (const float*)d_in[0];
    const float* anchors = (const float*)d_in[1];
    const float* fm      = (const float*)d_in[2];
    const float* kp      = (const float*)d_in[3];

    float* boxes_out = (float*)d_out;
    float* bev_out   = (float*)d_out + BOX_ELEMS;

    // 1. per-keypoint offsets + weights (tiny)
    precompute_kernel<<<(BB * KK + 255) / 256, 256>>>(kp);

    // 2. fused gather + decode
    cudaFuncSetAttribute(fused_kernel,
                         cudaFuncAttributeMaxDynamicSharedMemorySize, SMEM_BYTES);
    fused_kernel<<<TOTAL_BLOCKS, THREADS, SMEM_BYTES>>>(
        deltas, anchors, fm, boxes_out, bev_out);

    (void)in_sizes; (void)n_in; (void)out_size;
}

// round 14
// speedup vs baseline: 1.2504x; 1.2504x over previous
#include <cuda_runtime.h>
#include <cuda_fp16.h>

// ---------------- problem constants ----------------
#define BB    4
#define NANCH 211200
#define CC    256
#define HH    200
#define WW    176
#define KK    4096

#define NBOX      (BB * NANCH)          // 844,800
#define BOX_ELEMS (NBOX * 7)            // 5,913,600

#define THREADS   1024
#define KPT       (KK / THREADS)        // 4 points per thread

#define GATHER_BLOCKS (BB * CC)                 // 1024, one CTA per plane
#define DECODE_BLOCKS (NBOX / THREADS)          // 825 (exact)
#define TOTAL_BLOCKS  (GATHER_BLOCKS + DECODE_BLOCKS)  // 1849

#define PLANE_FLOATS (HH * WW)          // 35,200
#define SMEM_BYTES   (PLANE_FLOATS * 2) // 70,400 B (fp16 plane) -> 2 CTAs/SM

// Precomputed per-(b,k): 4 clamped corner offsets + 4 validity-folded weights.
__device__ ushort4 g_off[BB * KK];
__device__ float4  g_wgt[BB * KK];

__device__ __forceinline__ unsigned h2_bits(__half2 h) {
    union { __half2 h; unsigned u; } cvt;
    cvt.h = h;
    return cvt.u;
}

// ---------------- kernel 1: per-keypoint precompute ----------------
__global__ void precompute_kernel(const float* __restrict__ kp)
{
    int i = blockIdx.x * blockDim.x + threadIdx.x;
    if (i >= BB * KK) return;

    float x = kp[i * 3 + 0];
    float y = kp[i * 3 + 1];

    // --- coord transform (matches reference exactly) ---
    const float px = 0.05f * 8.0f;              // base_pixel_size * STRIDE
    float idx_x = x / px;
    float idx_y = (y + 40.0f) / px;
    idx_x = fminf(fmaxf(idx_x, 0.0f), (float)(WW - 1));
    idx_y = fminf(fmaxf(idx_y, 0.0f), (float)(HH - 1));
    float nx = 2.0f * (idx_x / (float)(WW - 2)) - 1.0f;
    float ny = 2.0f * (idx_y / (float)(HH - 2)) - 1.0f;
    // grid = flip(indices): width driven by ny, height by nx
    float ix = (ny + 1.0f) * 0.5f * (float)(WW - 1);
    float iy = (nx + 1.0f) * 0.5f * (float)(HH - 1);

    float x0f = floorf(ix);
    float y0f = floorf(iy);
    float wx = ix - x0f;
    float wy = iy - y0f;
    int x0 = (int)x0f, y0 = (int)y0f;
    int x1 = x0 + 1,   y1 = y0 + 1;

    float vx0 = (x0 >= 0 && x0 <= WW - 1) ? 1.0f : 0.0f;
    float vx1 = (x1 >= 0 && x1 <= WW - 1) ? 1.0f : 0.0f;
    float vy0 = (y0 >= 0 && y0 <= HH - 1) ? 1.0f : 0.0f;
    float vy1 = (y1 >= 0 && y1 <= HH - 1) ? 1.0f : 0.0f;

    int x0c = min(max(x0, 0), WW - 1);
    int x1c = min(max(x1, 0), WW - 1);
    int y0c = min(max(y0, 0), HH - 1);
    int y1c = min(max(y1, 0), HH - 1);

    g_off[i] = make_ushort4((unsigned short)(y0c * WW + x0c),
                            (unsigned short)(y0c * WW + x1c),
                            (unsigned short)(y1c * WW + x0c),
                            (unsigned short)(y1c * WW + x1c));
    g_wgt[i] = make_float4((1.0f - wx) * (1.0f - wy) * (vx0 * vy0),
                           wx          * (1.0f - wy) * (vx1 * vy0),
                           (1.0f - wx) * wy          * (vx0 * vy1),
                           wx          * wy          * (vx1 * vy1));
}

// ---------------- decode for one box ----------------
__device__ __forceinline__ void decode_one(const float* __restrict__ deltas,
                                           const float* __restrict__ anchors,
                                           float* __restrict__ out, int box)
{
    size_t base = (size_t)box * 7;
    float d0 = deltas[base + 0], d1 = deltas[base + 1], d2 = deltas[base + 2];
    float d3 = deltas[base + 3], d4 = deltas[base + 4], d5 = deltas[base + 5];
    float d6 = deltas[base + 6];
    float a0 = anchors[base + 0], a1 = anchors[base + 1], a2 = anchors[base + 2];
    float a3 = anchors[base + 3], a4 = anchors[base + 4], a5 = anchors[base + 5];
    float a6 = anchors[base + 6];

    float dnorm = sqrtf(a3 * a3 + a4 * a4);

    out[base + 0] = d0 * dnorm + a0;
    out[base + 1] = d1 * dnorm + a1;
    out[base + 2] = d2 * a5 + a2;
    out[base + 3] = expf(d3) * a3;
    out[base + 4] = expf(d4) * a4;
    out[base + 5] = expf(d5) * a5;
    out[base + 6] = d6 + a6;
}

// ---------------- gather: one (b,c) plane, fp16-staged ----------------
__device__ __forceinline__ void gather_plane(int pl,
                                             const float* __restrict__ fm,
                                             float* __restrict__ bev,
                                             __half* __restrict__ plane)
{
    const int b = pl >> 8;                      // pl / CC
    const float4* __restrict__ src =
        (const float4*)(fm + (size_t)pl * PLANE_FLOATS);
    uint2* __restrict__ dst = (uint2*)plane;

    // stage plane as fp16: 8800 float4 -> 8800 uint2 (half4)
    {
        const int N4   = PLANE_FLOATS / 4;      // 8800
        const int FULL = (N4 / THREADS) & ~7;   // 8
        int i = threadIdx.x;
        #pragma unroll 8
        for (int t = 0; t < FULL; t++, i += THREADS) {
            float4 v = src[i];
            __half2 h01 = __floats2half2_rn(v.x, v.y);
            __half2 h23 = __floats2half2_rn(v.z, v.w);
            dst[i] = make_uint2(h2_bits(h01), h2_bits(h23));
        }
        for (; i < N4; i += THREADS) {
            float4 v = src[i];
            __half2 h01 = __floats2half2_rn(v.x, v.y);
            __half2 h23 = __floats2half2_rn(v.z, v.w);
            dst[i] = make_uint2(h2_bits(h01), h2_bits(h23));
        }
    }
    __syncthreads();

    float* __restrict__ orow = bev + (size_t)pl * KK;
    const int base = b * KK + threadIdx.x;

    #pragma unroll
    for (int t = 0; t < KPT; t++) {
        int idx = base + t * THREADS;
        ushort4 o = __ldg(&g_off[idx]);
        float4  w = __ldg(&g_wgt[idx]);
        float r = __half2float(plane[o.x]) * w.x
                + __half2float(plane[o.y]) * w.y
                + __half2float(plane[o.z]) * w.z
                + __half2float(plane[o.w]) * w.w;
        orow[t * THREADS + threadIdx.x] = r;
    }
}

// ---------------- fused kernel ----------------
// Interleave gather / decode roles so each scheduling wave mixes streaming
// decode with smem gather work; 2 CTAs/SM overlap stage and gather phases.
__global__ void __launch_bounds__(THREADS, 2)
fused_kernel(const float* __restrict__ deltas,
             const float* __restrict__ anchors,
             const float* __restrict__ fm,
             float* __restrict__ boxes,
             float* __restrict__ bev)
{
    extern __shared__ __half smem[];
    const int blk = blockIdx.x;

    int gather_idx = -1, decode_idx = -1;
    if (blk < 2 * DECODE_BLOCKS) {              // first 1650 blocks alternate
        if (blk & 1) decode_idx = blk >> 1;
        else         gather_idx = blk >> 1;
    } else {
        gather_idx = blk - DECODE_BLOCKS;       // 825 .. 1023
    }

    if (gather_idx >= 0) {
        gather_plane(gather_idx, fm, bev, smem);
    } else {
        int box = decode_idx * THREADS + threadIdx.x;
        decode_one(deltas, anchors, boxes, box);
    }
}

// ---------------- launch ----------------
extern "C" void kernel_launch(void* const* d_in, const int* in_sizes, int n_in,
                              void* d_out, int out_size)
{
    const float* deltas  = (const float*)d_in[0];
    const float* anchors = (const float*)d_in[1];
    const float* fm      = (const float*)d_in[2];
    const float* kp      = (const float*)d_in[3];

    float* boxes_out = (float*)d_out;
    float* bev_out   = (float*)d_out + BOX_ELEMS;

    // 1. per-keypoint offsets + weights (tiny)
    precompute_kernel<<<(BB * KK + 255) / 256, 256>>>(kp);

    // 2. fused gather + decode
    cudaFuncSetAttribute(fused_kernel,
                         cudaFuncAttributeMaxDynamicSharedMemorySize, SMEM_BYTES);
    fused_kernel<<<TOTAL_BLOCKS, THREADS, SMEM_BYTES>>>(
        deltas, anchors, fm, boxes_out, bev_out);

    (void)in_sizes; (void)n_in; (void)out_size;
}

// round 15
// speedup vs baseline: 1.3416x; 1.0729x over previous
#include <cuda_runtime.h>
#include <cuda_fp16.h>

// ---------------- problem constants ----------------
#define BB    4
#define NANCH 211200
#define CC    256
#define HH    200
#define WW    176
#define KK    4096

#define NBOX      (BB * NANCH)          // 844,800
#define BOX_ELEMS (NBOX * 7)            // 5,913,600

#define THREADS   1024
#define KPT       (KK / THREADS)        // 4 points per thread

#define GATHER_BLOCKS (BB * CC)                 // 1024, one CTA per plane
#define DECODE_BLOCKS (NBOX / THREADS)          // 825 (exact)
#define TOTAL_BLOCKS  (GATHER_BLOCKS + DECODE_BLOCKS)  // 1849

#define PLANE_FLOATS (HH * WW)          // 35,200
#define SMEM_BYTES   (PLANE_FLOATS * 2) // 70,400 B (fp16 plane) -> 2 CTAs/SM

__device__ __forceinline__ unsigned h2_bits(__half2 h) {
    union { __half2 h; unsigned u; } cvt;
    cvt.h = h;
    return cvt.u;
}

// ---------------- decode for one box ----------------
__device__ __forceinline__ void decode_one(const float* __restrict__ deltas,
                                           const float* __restrict__ anchors,
                                           float* __restrict__ out, int box)
{
    size_t base = (size_t)box * 7;
    float d0 = deltas[base + 0], d1 = deltas[base + 1], d2 = deltas[base + 2];
    float d3 = deltas[base + 3], d4 = deltas[base + 4], d5 = deltas[base + 5];
    float d6 = deltas[base + 6];
    float a0 = anchors[base + 0], a1 = anchors[base + 1], a2 = anchors[base + 2];
    float a3 = anchors[base + 3], a4 = anchors[base + 4], a5 = anchors[base + 5];
    float a6 = anchors[base + 6];

    float dnorm = sqrtf(a3 * a3 + a4 * a4);

    out[base + 0] = d0 * dnorm + a0;
    out[base + 1] = d1 * dnorm + a1;
    out[base + 2] = d2 * a5 + a2;
    out[base + 3] = expf(d3) * a3;
    out[base + 4] = expf(d4) * a4;
    out[base + 5] = expf(d5) * a5;
    out[base + 6] = d6 + a6;
}

// ---------------- gather: one (b,c) plane, fp16-staged, inline coords ------
__device__ __forceinline__ void gather_plane(int pl,
                                             const float* __restrict__ fm,
                                             const float* __restrict__ kp,
                                             float* __restrict__ bev,
                                             __half* __restrict__ plane)
{
    const int b = pl >> 8;                      // pl / CC
    const float4* __restrict__ src =
        (const float4*)(fm + (size_t)pl * PLANE_FLOATS);
    uint2* __restrict__ dst = (uint2*)plane;

    // stage plane as fp16: 8800 float4 -> 8800 uint2 (half4)
    {
        const int N4   = PLANE_FLOATS / 4;      // 8800
        const int FULL = (N4 / THREADS) & ~7;   // 8
        int i = threadIdx.x;
        #pragma unroll 8
        for (int t = 0; t < FULL; t++, i += THREADS) {
            float4 v = src[i];
            __half2 h01 = __floats2half2_rn(v.x, v.y);
            __half2 h23 = __floats2half2_rn(v.z, v.w);
            dst[i] = make_uint2(h2_bits(h01), h2_bits(h23));
        }
        for (; i < N4; i += THREADS) {
            float4 v = src[i];
            __half2 h01 = __floats2half2_rn(v.x, v.y);
            __half2 h23 = __floats2half2_rn(v.z, v.w);
            dst[i] = make_uint2(h2_bits(h01), h2_bits(h23));
        }
    }
    __syncthreads();

    const float* __restrict__ kpb  = kp  + (size_t)b * KK * 3;
    float*       __restrict__ orow = bev + (size_t)pl * KK;

    #pragma unroll
    for (int t = 0; t < KPT; t++) {
        int k = t * THREADS + threadIdx.x;
        float x = __ldg(kpb + k * 3 + 0);
        float y = __ldg(kpb + k * 3 + 1);

        // --- coord transform (matches reference exactly) ---
        const float px = 0.05f * 8.0f;          // base_pixel_size * STRIDE
        float idx_x = x / px;
        float idx_y = (y + 40.0f) / px;
        idx_x = fminf(fmaxf(idx_x, 0.0f), (float)(WW - 1));
        idx_y = fminf(fmaxf(idx_y, 0.0f), (float)(HH - 1));
        float nx = 2.0f * (idx_x / (float)(WW - 2)) - 1.0f;
        float ny = 2.0f * (idx_y / (float)(HH - 2)) - 1.0f;
        // grid = flip(indices): width driven by ny, height by nx
        float ix = (ny + 1.0f) * 0.5f * (float)(WW - 1);
        float iy = (nx + 1.0f) * 0.5f * (float)(HH - 1);

        float x0f = floorf(ix);
        float y0f = floorf(iy);
        float wx = ix - x0f;
        float wy = iy - y0f;
        int x0 = (int)x0f, y0 = (int)y0f;
        int x1 = x0 + 1,   y1 = y0 + 1;

        float vx0 = (x0 >= 0 && x0 <= WW - 1) ? 1.0f : 0.0f;
        float vx1 = (x1 >= 0 && x1 <= WW - 1) ? 1.0f : 0.0f;
        float vy0 = (y0 >= 0 && y0 <= HH - 1) ? 1.0f : 0.0f;
        float vy1 = (y1 >= 0 && y1 <= HH - 1) ? 1.0f : 0.0f;

        int x0c = min(max(x0, 0), WW - 1);
        int x1c = min(max(x1, 0), WW - 1);
        int y0c = min(max(y0, 0), HH - 1);
        int y1c = min(max(y1, 0), HH - 1);

        float w00 = (1.0f - wx) * (1.0f - wy) * (vx0 * vy0);
        float w01 = wx          * (1.0f - wy) * (vx1 * vy0);
        float w10 = (1.0f - wx) * wy          * (vx0 * vy1);
        float w11 = wx          * wy          * (vx1 * vy1);

        float r = __half2float(plane[y0c * WW + x0c]) * w00
                + __half2float(plane[y0c * WW + x1c]) * w01
                + __half2float(plane[y1c * WW + x0c]) * w10
                + __half2float(plane[y1c * WW + x1c]) * w11;

        orow[k] = r;
    }
}

// ---------------- fused kernel ----------------
// Bresenham even-spread of 1024 gather : 825 decode roles across the whole
// grid so every scheduling wave (incl. tail) mixes streaming decode with
// smem gather; 2 CTAs/SM overlap stage and gather phases.
__global__ void __launch_bounds__(THREADS, 2)
fused_kernel(const float* __restrict__ deltas,
             const float* __restrict__ anchors,
             const float* __restrict__ fm,
             const float* __restrict__ kp,
             float* __restrict__ boxes,
             float* __restrict__ bev)
{
    extern __shared__ __half smem[];
    const int blk = blockIdx.x;

    // gathers among blocks [0, blk) = floor(blk*G/T); block blk is a gather
    // iff the count increments at blk.
    const int p = (blk * GATHER_BLOCKS) / TOTAL_BLOCKS;
    const int c = ((blk + 1) * GATHER_BLOCKS) / TOTAL_BLOCKS;

    if (c > p) {
        gather_plane(p, fm, kp, bev, smem);
    } else {
        int box = (blk - p) * THREADS + threadIdx.x;
        decode_one(deltas, anchors, boxes, box);
    }
}

// ---------------- launch ----------------
extern "C" void kernel_launch(void* const* d_in, const int* in_sizes, int n_in,
                              void* d_out, int out_size)
{
    const float* deltas  = (const float*)d_in[0];
    const float* anchors = (const float*)d_in[1];
    const float* fm      = (const float*)d_in[2];
    const float* kp      = (const float*)d_in[3];

    float* boxes_out = (float*)d_out;
    float* bev_out   = (float*)d_out + BOX_ELEMS;

    cudaFuncSetAttribute(fused_kernel,
                         cudaFuncAttributeMaxDynamicSharedMemorySize, SMEM_BYTES);
    fused_kernel<<<TOTAL_BLOCKS, THREADS, SMEM_BYTES>>>(
        deltas, anchors, fm, kp, boxes_out, bev_out);

    (void)in_sizes; (void)n_in; (void)out_size;
}

// round 16
// speedup vs baseline: 1.4057x; 1.0478x over previous
#include <cuda_runtime.h>
#include <cuda_fp16.h>

// ---------------- problem constants ----------------
#define BB    4
#define NANCH 211200
#define CC    256
#define HH    200
#define WW    176
#define KK    4096

#define NBOX      (BB * NANCH)          // 844,800
#define BOX_ELEMS (NBOX * 7)            // 5,913,600

#define THREADS   1024
#define KPT       (KK / THREADS)        // 4 points per thread

#define GATHER_BLOCKS (BB * CC)                 // 1024, one CTA per plane
#define DECODE_BLOCKS (NBOX / THREADS)          // 825 (exact)
#define TOTAL_BLOCKS  (GATHER_BLOCKS + DECODE_BLOCKS)  // 1849

#define PLANE_FLOATS (HH * WW)          // 35,200
#define SMEM_BYTES   (PLANE_FLOATS * 2) // 70,400 B (fp16 plane) -> 2 CTAs/SM

__device__ __forceinline__ unsigned h2_bits(__half2 h) {
    union { __half2 h; unsigned u; } cvt;
    cvt.h = h;
    return cvt.u;
}

// ---------------- decode for one box ----------------
__device__ __forceinline__ void decode_one(const float* __restrict__ deltas,
                                           const float* __restrict__ anchors,
                                           float* __restrict__ out, int box)
{
    size_t base = (size_t)box * 7;
    float d0 = deltas[base + 0], d1 = deltas[base + 1], d2 = deltas[base + 2];
    float d3 = deltas[base + 3], d4 = deltas[base + 4], d5 = deltas[base + 5];
    float d6 = deltas[base + 6];
    float a0 = anchors[base + 0], a1 = anchors[base + 1], a2 = anchors[base + 2];
    float a3 = anchors[base + 3], a4 = anchors[base + 4], a5 = anchors[base + 5];
    float a6 = anchors[base + 6];

    float dnorm = sqrtf(a3 * a3 + a4 * a4);

    out[base + 0] = d0 * dnorm + a0;
    out[base + 1] = d1 * dnorm + a1;
    out[base + 2] = d2 * a5 + a2;
    out[base + 3] = expf(d3) * a3;
    out[base + 4] = expf(d4) * a4;
    out[base + 5] = expf(d5) * a5;
    out[base + 6] = d6 + a6;
}

// ---------------- gather: one (b,c) plane, fp16-staged ----------------
// Coord chain collapsed algebraically:
//   ix = clamp((y+40)/0.4, 0, 199) * 175/198   (width  coord, in [0, 175.89])
//   iy = clamp( x    /0.4, 0, 175) * 199/174   (height coord, in [0, 200.15])
// => x0 always in [0,175] (vx0 always true); only 3 predicates remain.
__device__ __forceinline__ void gather_plane(int pl,
                                             const float* __restrict__ fm,
                                             const float* __restrict__ kp,
                                             float* __restrict__ bev,
                                             __half* __restrict__ plane)
{
    const int b = pl >> 8;                      // pl / CC
    const float4* __restrict__ src =
        (const float4*)(fm + (size_t)pl * PLANE_FLOATS);
    uint2* __restrict__ dst = (uint2*)plane;

    // stage plane as fp16: 8800 float4 -> 8800 uint2 (half4)
    {
        const int N4   = PLANE_FLOATS / 4;      // 8800
        const int FULL = (N4 / THREADS) & ~7;   // 8
        int i = threadIdx.x;
        #pragma unroll 8
        for (int t = 0; t < FULL; t++, i += THREADS) {
            float4 v = src[i];
            __half2 h01 = __floats2half2_rn(v.x, v.y);
            __half2 h23 = __floats2half2_rn(v.z, v.w);
            dst[i] = make_uint2(h2_bits(h01), h2_bits(h23));
        }
        for (; i < N4; i += THREADS) {
            float4 v = src[i];
            __half2 h01 = __floats2half2_rn(v.x, v.y);
            __half2 h23 = __floats2half2_rn(v.z, v.w);
            dst[i] = make_uint2(h2_bits(h01), h2_bits(h23));
        }
    }
    __syncthreads();

    const float* __restrict__ kpb  = kp  + (size_t)b * KK * 3;
    float*       __restrict__ orow = bev + (size_t)pl * KK;

    // prefetch all KPT points' (x,y) up-front for MLP
    float xv[KPT], yv[KPT];
    #pragma unroll
    for (int t = 0; t < KPT; t++) {
        int k = t * THREADS + threadIdx.x;
        xv[t] = __ldg(kpb + k * 3 + 0);
        yv[t] = __ldg(kpb + k * 3 + 1);
    }

    const float px = 0.05f * 8.0f;              // 0.4
    const float SX = 175.0f / 198.0f;           // (W-1)/(H-2)
    const float SY = 199.0f / 174.0f;           // (H-1)/(W-2)

    #pragma unroll
    for (int t = 0; t < KPT; t++) {
        float ix = fminf(fmaxf((yv[t] + 40.0f) / px, 0.0f), 199.0f) * SX;
        float iy = fminf(fmaxf( xv[t]          / px, 0.0f), 175.0f) * SY;

        int x0 = (int)ix;                       // trunc == floor (ix >= 0)
        int y0 = (int)iy;
        float wx = ix - (float)x0;
        float wy = iy - (float)y0;

        // only upper-bound validity can fail
        float vx1 = (x0 < WW - 1) ? 1.0f : 0.0f;    // x1 valid
        float vy0 = (y0 <= HH - 1) ? 1.0f : 0.0f;   // y0 valid (y0 can be 200)
        float vy1 = (y0 <  HH - 1) ? 1.0f : 0.0f;   // y1 valid

        int x1c = min(x0 + 1, WW - 1);
        int y0c = min(y0,     HH - 1);
        int y1c = min(y0 + 1, HH - 1);

        float w00 = (1.0f - wx) * (1.0f - wy) * vy0;
        float w01 = wx          * (1.0f - wy) * (vx1 * vy0);
        float w10 = (1.0f - wx) * wy          * vy1;
        float w11 = wx          * wy          * (vx1 * vy1);

        int r0 = y0c * WW;
        int r1 = y1c * WW;
        float r = __half2float(plane[r0 + x0 ]) * w00
                + __half2float(plane[r0 + x1c]) * w01
                + __half2float(plane[r1 + x0 ]) * w10
                + __half2float(plane[r1 + x1c]) * w11;

        orow[t * THREADS + threadIdx.x] = r;
    }
}

// ---------------- fused kernel ----------------
// Bresenham even-spread of 1024 gather : 825 decode roles across the whole
// grid so every scheduling wave (incl. tail) mixes streaming decode with
// smem gather; 2 CTAs/SM overlap stage and gather phases.
__global__ void __launch_bounds__(THREADS, 2)
fused_kernel(const float* __restrict__ deltas,
             const float* __restrict__ anchors,
             const float* __restrict__ fm,
             const float* __restrict__ kp,
             float* __restrict__ boxes,
             float* __restrict__ bev)
{
    extern __shared__ __half smem[];
    const int blk = blockIdx.x;

    const int p = (blk * GATHER_BLOCKS) / TOTAL_BLOCKS;
    const int c = ((blk + 1) * GATHER_BLOCKS) / TOTAL_BLOCKS;

    if (c > p) {
        gather_plane(p, fm, kp, bev, smem);
    } else {
        int box = (blk - p) * THREADS + threadIdx.x;
        decode_one(deltas, anchors, boxes, box);
    }
}

// ---------------- launch ----------------
extern "C" void kernel_launch(void* const* d_in, const int* in_sizes, int n_in,
                              void* d_out, int out_size)
{
    const float* deltas  = (const float*)d_in[0];
    const float* anchors = (const float*)d_in[1];
    const float* fm      = (const float*)d_in[2];
    const float* kp      = (const float*)d_in[3];

    float* boxes_out = (float*)d_out;
    float* bev_out   = (float*)d_out + BOX_ELEMS;

    cudaFuncSetAttribute(fused_kernel,
                         cudaFuncAttributeMaxDynamicSharedMemorySize, SMEM_BYTES);
    fused_kernel<<<TOTAL_BLOCKS, THREADS, SMEM_BYTES>>>(
        deltas, anchors, fm, kp, boxes_out, bev_out);

    (void)in_sizes; (void)n_in; (void)out_size;
}